// round 16
// baseline (speedup 1.0000x reference)
#include <cuda_runtime.h>
#include <cuda_fp16.h>
#include <cstdint>
#include <cstddef>

// Problem dims
#define NB   128     // batch
#define NT   256     // time steps
#define HD   1024    // hidden
#define IN   150     // input feature (J*D)
#define INP  192     // padded input feature
#define NC   60      // classes
#define G4   4096    // 4*HD

// Packed tile geometry: k-tile = 64 halves (128B rows, SW128 swizzled)
#define KT       64
#define AHALVES  16384          // A tile block: 256 rows (hi 0-127, lo 128-255) x 64 halves
#define WTILEH   (4096 * 64)    // weight tile block: 4096 n-rows x 64 halves
#define XSTEPH   (3 * AHALVES)  // x per step: 3 tiles

// smem stages
#define ATB   32768             // A tile bytes
#define BTB   8192              // B tile bytes
#define STB   (ATB + BTB)       // 40960
#define NST   4
#define SMEM_BODY (NST * STB)   // 163840
#define GS_STRIDE 129
#define SMEM_DYN (SMEM_BODY + 1024 + 512)   // pad for 1KB align + mbars + bias

// ---------------- persistent device state (packed, pre-swizzled) ----------------
__device__ __half g_h1e[2][16 * AHALVES];
__device__ __half g_h2e[2][16 * AHALVES];
__device__ float g_c1[NB * HD];
__device__ float g_c2[NB * HD];
__device__ float g_bias1e[G4];              // reordered n = u*4+g
__device__ float g_bias2e[G4];
__device__ __half g_whh1p[16 * WTILEH];
__device__ __half g_wih2p[16 * WTILEH];
__device__ __half g_whh2p[16 * WTILEH];
__device__ __half g_wih1p[3 * WTILEH];
__device__ __half g_xp[NT * XSTEPH];

// ---------------- PTX helpers ----------------
__device__ __forceinline__ uint32_t smem_u32(const void* p) {
    uint32_t a;
    asm("{ .reg .u64 t; cvta.to.shared.u64 t, %1; cvt.u32.u64 %0, t; }" : "=r"(a) : "l"(p));
    return a;
}
__device__ __forceinline__ void cpbulk(uint32_t dst, const void* src, uint32_t bytes, uint32_t mbar) {
    asm volatile("cp.async.bulk.shared::cta.global.mbarrier::complete_tx::bytes [%0], [%1], %2, [%3];"
                 :: "r"(dst), "l"(src), "r"(bytes), "r"(mbar) : "memory");
}
#define MBAR_INIT(a, cnt) asm volatile("mbarrier.init.shared.b64 [%0], %1;" :: "r"(a), "r"(cnt) : "memory")
#define MBAR_EXPECT_TX(a, bytes) \
    asm volatile("mbarrier.arrive.expect_tx.shared.b64 _, [%0], %1;" :: "r"(a), "r"((uint32_t)(bytes)) : "memory")
#define MBAR_ARRIVE(a) \
    asm volatile("mbarrier.arrive.shared.b64 _, [%0];" :: "r"(a) : "memory")
#define MBAR_WAIT(a, par) do {                                                   \
    uint32_t _d = 0;                                                             \
    while (!_d) {                                                                \
        asm volatile("{ .reg .pred p; mbarrier.try_wait.parity.shared.b64 p, [%1], %2; selp.b32 %0,1,0,p; }" \
            : "=r"(_d) : "r"(a), "r"((uint32_t)(par)) : "memory");               \
    }                                                                            \
} while (0)

__device__ __forceinline__ void ldsm4(uint32_t* r, uint32_t addr) {
    asm volatile("ldmatrix.sync.aligned.m8n8.x4.shared.b16 {%0,%1,%2,%3}, [%4];"
                 : "=r"(r[0]), "=r"(r[1]), "=r"(r[2]), "=r"(r[3]) : "r"(addr));
}
__device__ __forceinline__ void mma16816(float* d, const uint32_t* a, const uint32_t* b) {
    asm volatile(
        "mma.sync.aligned.m16n8k16.row.col.f32.f16.f16.f32 "
        "{%0,%1,%2,%3}, {%4,%5,%6,%7}, {%8,%9}, {%0,%1,%2,%3};"
        : "+f"(d[0]), "+f"(d[1]), "+f"(d[2]), "+f"(d[3])
        : "r"(a[0]), "r"(a[1]), "r"(a[2]), "r"(a[3]), "r"(b[0]), "r"(b[1]));
}

__device__ __forceinline__ float sigf(float x) { return 1.0f / (1.0f + __expf(-x)); }
__device__ __forceinline__ float tanh_f(float x) { return 2.0f / (1.0f + __expf(-2.0f * x)) - 1.0f; }

// swizzled half-index within a tile block row: row r, half-col kl (0..63)
__device__ __forceinline__ int swh(int r, int kl) {
    return ((kl * 2) ^ ((r & 7) << 4)) >> 1;
}

// ---------------- single merged prep kernel ----------------
__device__ __forceinline__ void conv_w_packed(const float* W, __half* out, int K, int KP, int idx) {
    if (idx >= G4 * KP) return;
    int n = idx / KP, k = idx % KP;
    int g = n & 3, u = n >> 2;
    float v = (k < K) ? W[(size_t)(g * HD + u) * K + k] : 0.0f;
    int tile = k >> 6, kl = k & 63;
    out[(size_t)tile * WTILEH + (size_t)n * 64 + swh(n, kl)] = __float2half(v);
}

__global__ void prep_all(const float* __restrict__ x,
                         const float* __restrict__ h1, const float* __restrict__ c1,
                         const float* __restrict__ h2, const float* __restrict__ c2,
                         const float* __restrict__ bih1, const float* __restrict__ bhh1,
                         const float* __restrict__ bih2, const float* __restrict__ bhh2,
                         const float* __restrict__ Wih1, const float* __restrict__ Whh1,
                         const float* __restrict__ Wih2, const float* __restrict__ Whh2) {
    int idx = blockIdx.x * blockDim.x + threadIdx.x;
    int task = blockIdx.y;
    if (task == 0) {
        if (idx < NB * HD) {
            int m = idx / HD, u = idx % HD;
            float v1 = h1[idx], v2 = h2[idx];
            __half h1hi = __float2half(v1);
            __half h1lo = __float2half(v1 - __half2float(h1hi));
            __half h2hi = __float2half(v2);
            __half h2lo = __float2half(v2 - __half2float(h2hi));
            int tile = u >> 6, kl = u & 63;
            size_t base = (size_t)tile * AHALVES + (size_t)m * 64 + swh(m, kl);
            g_h1e[0][base] = h1hi; g_h1e[0][base + 8192] = h1lo;
            g_h2e[0][base] = h2hi; g_h2e[0][base + 8192] = h2lo;
            g_c1[idx] = c1[idx];
            g_c2[idx] = c2[idx];
        }
        if (idx < G4) {
            int g = idx & 3, u = idx >> 2;
            int r = g * HD + u;
            g_bias1e[idx] = bih1[r] + bhh1[r];
            g_bias2e[idx] = bih2[r] + bhh2[r];
        }
    } else if (task == 1) {
        conv_w_packed(Whh1, g_whh1p, HD, HD, idx);
    } else if (task == 2) {
        conv_w_packed(Wih2, g_wih2p, HD, HD, idx);
    } else if (task == 3) {
        conv_w_packed(Whh2, g_whh2p, HD, HD, idx);
    } else if (task == 4) {
        conv_w_packed(Wih1, g_wih1p, IN, INP, idx);
    } else {
        if (idx >= NT * NB * INP) return;
        int k = idx % INP;
        int r = idx / INP;
        int b = r % NB, t = r / NB;
        float v = (k < IN) ? x[((size_t)b * NT + t) * IN + k] : 0.0f;
        __half hi = __float2half(v);
        __half lo = __float2half(v - __half2float(hi));
        int tile = k >> 6, kl = k & 63;
        size_t base = (size_t)t * XSTEPH + (size_t)tile * AHALVES + (size_t)b * 64 + swh(b, kl);
        g_xp[base] = hi;
        g_xp[base + 8192] = lo;
    }
}

// ---------------- combined LSTM step kernel ----------------
// tl = 0..NT.  blockIdx.z==1: role1 (phase1 at t=tl-1)  [skip tl==0]
//              blockIdx.z==0: role0 (phase0 at t=tl)    [skip tl==NT]
// grid = (64 n-tiles, 1, 2 roles) = 128 CTAs, 1/SM. block = 512 (16 warps, 16m x 32n).
// Producer/consumer mbarrier pipeline (no __syncthreads in mainloop).
// Split accumulators: dh (Ah pass) and dl (Al pass) -> all 8 mma per kk independent.
__global__ void __launch_bounds__(512)
lstm_step_combined(int tl) {
    const int role = blockIdx.z;
    if (role == 0 && tl == NT) return;
    if (role == 1 && tl == 0) return;
    const int t = (role == 0) ? tl : (tl - 1);
    const int cur = t & 1;
    const int n0 = blockIdx.x * 64;

    extern __shared__ __align__(16) char raw[];
    const uint32_t SB = (smem_u32(raw) + 1023u) & ~1023u;
    char* base = raw + (SB - smem_u32(raw));
    float* Gs    = (float*)base;                       // aliases stages (after loop)
    float* biasS = (float*)(base + SMEM_BODY + 128);   // after mbarriers
    const uint32_t MBF = SB + SMEM_BODY;               // 4 full barriers
    const uint32_t MBE = MBF + 32;                     // 4 empty barriers

    const int tid  = threadIdx.x;
    const int wid  = tid >> 5;
    const int lane = tid & 31;

    const __half *Ap0, *Ap1, *Bp0, *Bp1;
    const float* biasE;
    float* cst;
    __half* houtP;
    int T1;
    if (role == 0) {
        Ap0 = g_h1e[cur];      Bp0 = g_whh1p;
        Ap1 = g_xp + (size_t)t * XSTEPH;  Bp1 = g_wih1p;
        T1 = 3;
        biasE = g_bias1e; cst = g_c1; houtP = g_h1e[cur ^ 1];
    } else {
        Ap0 = g_h1e[cur ^ 1];  Bp0 = g_wih2p;
        Ap1 = g_h2e[cur];      Bp1 = g_whh2p;
        T1 = 16;
        biasE = g_bias2e; cst = g_c2; houtP = g_h2e[cur ^ 1];
    }
    const int T0 = 16;
    const int TT = T0 + T1;          // 32 or 19

    if (tid == 0) {
#pragma unroll
        for (int s = 0; s < NST; s++) {
            MBAR_INIT(MBF + 8 * s, 1);
            MBAR_INIT(MBE + 8 * s, 16);
        }
    }
    __syncthreads();

    auto issue = [&](int c) {
        const int s = c & (NST - 1);
        const __half *sa, *sb;
        if (c < T0) { sa = Ap0 + (size_t)c * AHALVES;        sb = Bp0 + ((size_t)c * 4096 + n0) * 64; }
        else        { sa = Ap1 + (size_t)(c - T0) * AHALVES; sb = Bp1 + ((size_t)(c - T0) * 4096 + n0) * 64; }
        const uint32_t mb = MBF + 8u * s;
        MBAR_EXPECT_TX(mb, ATB + BTB);
        cpbulk(SB + s * STB, sa, ATB, mb);
        cpbulk(SB + s * STB + ATB, sb, BTB, mb);
    };
    if (tid == 0) { issue(0); issue(1); issue(2); }

    float biasR = (tid < 64) ? biasE[n0 + tid] : 0.0f;

    // ldmatrix lane maps (SW128 swizzle; rows are 128B)
    const int wr = wid >> 1;      // m sixteenth (0..7), rows wr*16..+15
    const int wc = wid & 1;       // n half
    const int grp = lane >> 3, lr = lane & 7;
    const uint32_t xm = (uint32_t)(lr << 4);
    const uint32_t arowH = (uint32_t)((wr * 16 + lr + (grp & 1) * 8) * 128);
    uint32_t brow[2];
#pragma unroll
    for (int nc = 0; nc < 2; nc++)
        brow[nc] = (uint32_t)((wc * 32 + nc * 16 + lr + (grp >> 1) * 8) * 128) + ATB;
    uint32_t acol[4], bcol[4];
#pragma unroll
    for (int kk = 0; kk < 4; kk++) {
        acol[kk] = (uint32_t)(((grp >> 1) * 16 + kk * 32)) ^ xm;
        bcol[kk] = (uint32_t)(((grp & 1) * 16 + kk * 32)) ^ xm;
    }

    // split accumulators: dh for Ah pass, dl for Al pass (8 independent chains)
    float dh[4][4], dl[4][4];
#pragma unroll
    for (int nj = 0; nj < 4; nj++)
#pragma unroll
        for (int q = 0; q < 4; q++) { dh[nj][q] = 0.0f; dl[nj][q] = 0.0f; }

    for (int c = 0; c < TT; c++) {
        const int s = c & (NST - 1);

        // producer: refill stage (c+3)&3 once tile c-1 consumers drained it
        if (tid == 0 && c + 3 < TT) {
            if (c >= 1) {
                const int cn = c + 3;
                MBAR_WAIT(MBE + 8u * (cn & (NST - 1)), (uint32_t)(((cn >> 2) - 1) & 1));
            }
            issue(c + 3);
        }

        // consumer: wait for this tile's data
        MBAR_WAIT(MBF + 8u * s, (uint32_t)((c >> 2) & 1));

        const uint32_t sb = SB + s * STB;
#pragma unroll
        for (int kk = 0; kk < 4; kk++) {
            uint32_t ah[4], al[4], b0r[4], b1r[4];
            ldsm4(b0r, sb + brow[0] + bcol[kk]);
            ldsm4(b1r, sb + brow[1] + bcol[kk]);
            ldsm4(ah,  sb + arowH + acol[kk]);
            ldsm4(al,  sb + arowH + 16384 + acol[kk]);
            // 8 mma, all on distinct accumulators -> no intra-kk RAW
            mma16816(dh[0], ah, b0r + 0);
            mma16816(dl[0], al, b0r + 0);
            mma16816(dh[1], ah, b0r + 2);
            mma16816(dl[1], al, b0r + 2);
            mma16816(dh[2], ah, b1r + 0);
            mma16816(dl[2], al, b1r + 0);
            mma16816(dh[3], ah, b1r + 2);
            mma16816(dl[3], al, b1r + 2);
        }
        if (lane == 0) MBAR_ARRIVE(MBE + 8u * s);   // this warp done with stage s
    }
    __syncthreads();   // re-converge warps; stage smem now reusable as Gs

    if (tid < 64) biasS[tid] = biasR;

    // acc -> Gs [n][m] (sum the two passes here)
#pragma unroll
    for (int nj = 0; nj < 4; nj++) {
        int r0 = wr * 16 + (lane >> 2);
        int cb = wc * 32 + nj * 8 + (lane & 3) * 2;
        Gs[cb * GS_STRIDE + r0]           = dh[nj][0] + dl[nj][0];
        Gs[(cb + 1) * GS_STRIDE + r0]     = dh[nj][1] + dl[nj][1];
        Gs[cb * GS_STRIDE + r0 + 8]       = dh[nj][2] + dl[nj][2];
        Gs[(cb + 1) * GS_STRIDE + r0 + 8] = dh[nj][3] + dl[nj][3];
    }
    __syncthreads();

    // cell update: 128 m x 16 u = 2048 cells, 4 per thread; h written packed+swizzled
    const int ubase = n0 >> 2;
#pragma unroll
    for (int r = 0; r < 4; r++) {
        int idx = tid + r * 512;
        int ml = idx & 127;     // m
        int u  = idx >> 7;      // 0..15
        int nb = u * 4;
        float gi_ = Gs[(nb + 0) * GS_STRIDE + ml] + biasS[nb + 0];
        float gf_ = Gs[(nb + 1) * GS_STRIDE + ml] + biasS[nb + 1];
        float gg_ = Gs[(nb + 2) * GS_STRIDE + ml] + biasS[nb + 2];
        float go_ = Gs[(nb + 3) * GS_STRIDE + ml] + biasS[nb + 3];
        int ug = ubase + u;
        int off = ml * HD + ug;
        float cv = cst[off];
        float cn = sigf(gf_) * cv + sigf(gi_) * tanh_f(gg_);
        cst[off] = cn;
        float h = sigf(go_) * tanh_f(cn);
        __half hi = __float2half(h);
        __half lo = __float2half(h - __half2float(hi));
        int tile = ug >> 6, kl = ug & 63;
        size_t hb = (size_t)tile * AHALVES + (size_t)ml * 64 + swh(ml, kl);
        houtP[hb] = hi;
        houtP[hb + 8192] = lo;
    }
}

// ---------------- final FC: out = h2 @ Wfc^T + bfc ----------------
__global__ void fc_kernel(const float* __restrict__ Wfc, const float* __restrict__ bfc,
                          float* __restrict__ out) {
    int b = blockIdx.x;
    int c = blockIdx.y;
    int lane = threadIdx.x;
    // last phase1 (t=NT-1, odd) wrote g_h2e[0]
    const __half* he = g_h2e[0];
    const float* w = Wfc + (size_t)c * HD;
    float s = 0.0f;
    for (int k = lane; k < HD; k += 32) {
        int tile = k >> 6, kl = k & 63;
        size_t idx = (size_t)tile * AHALVES + (size_t)b * 64 + swh(b, kl);
        float h = __half2float(he[idx]) + __half2float(he[idx + 8192]);
        s += h * w[k];
    }
#pragma unroll
    for (int o = 16; o > 0; o >>= 1) s += __shfl_xor_sync(0xFFFFFFFFu, s, o);
    if (lane == 0) out[b * NC + c] = s + bfc[c];
}

// ---------------- launch ----------------
extern "C" void kernel_launch(void* const* d_in, const int* in_sizes, int n_in,
                              void* d_out, int out_size) {
    (void)in_sizes; (void)n_in; (void)out_size;
    const float* x    = (const float*)d_in[0];
    const float* h1   = (const float*)d_in[1];
    const float* c1   = (const float*)d_in[2];
    const float* h2   = (const float*)d_in[3];
    const float* c2   = (const float*)d_in[4];
    const float* Wih1 = (const float*)d_in[5];
    const float* Whh1 = (const float*)d_in[6];
    const float* bih1 = (const float*)d_in[7];
    const float* bhh1 = (const float*)d_in[8];
    const float* Wih2 = (const float*)d_in[9];
    const float* Whh2 = (const float*)d_in[10];
    const float* bih2 = (const float*)d_in[11];
    const float* bhh2 = (const float*)d_in[12];
    const float* Wfc  = (const float*)d_in[13];
    const float* bfc  = (const float*)d_in[14];
    float* out = (float*)d_out;

    static int smem_set = 0;
    if (!smem_set) {
        cudaFuncSetAttribute(lstm_step_combined, cudaFuncAttributeMaxDynamicSharedMemorySize, SMEM_DYN);
        smem_set = 1;
    }

    // one-time prep (single launch)
    {
        dim3 pgrid((NT * NB * INP + 255) / 256, 6);
        prep_all<<<pgrid, 256>>>(x, h1, c1, h2, c2, bih1, bhh1, bih2, bhh2,
                                 Wih1, Whh1, Wih2, Whh2);
    }

    // recurrence: one combined launch per step boundary
    dim3 grid(G4 / 64, 1, 2);   // 128 CTAs
    for (int tl = 0; tl <= NT; tl++) {
        lstm_step_combined<<<grid, 512, SMEM_DYN>>>(tl);
    }

    fc_kernel<<<dim3(NB, NC), 32>>>(Wfc, bfc, out);
}

// round 17
// speedup vs baseline: 1.3173x; 1.3173x over previous
#include <cuda_runtime.h>
#include <cuda_fp16.h>
#include <cstdint>
#include <cstddef>

// Problem dims
#define NB   128     // batch
#define NT   256     // time steps
#define HD   1024    // hidden
#define IN   150     // input feature (J*D)
#define INP  192     // padded input feature
#define NC   60      // classes
#define G4   4096    // 4*HD

// Packed tile geometry: k-tile = 64 halves (128B rows, SW128 swizzled)
#define KT       64
#define ATILEH   8192           // A tile block: 128 rows x 64 halves (single fp16)
#define WTILEH   (4096 * 64)    // weight tile block: 4096 n-rows x 64 halves
#define XSTEPH   (3 * ATILEH)   // x per step: 3 tiles

// smem stages
#define ATB   16384             // A tile bytes
#define BTB   8192              // B tile bytes
#define STB   (ATB + BTB)       // 24576
#define NST   4
#define SMEM_BODY (NST * STB)   // 98304
#define GS_STRIDE 129
#define SMEM_DYN (SMEM_BODY + 1024 + 512)

// ---------------- persistent device state (packed, pre-swizzled, single fp16) ----
__device__ __half g_h1e[2][16 * ATILEH];
__device__ __half g_h2e[2][16 * ATILEH];
__device__ float g_c1[NB * HD];
__device__ float g_c2[NB * HD];
__device__ float g_bias1e[G4];              // reordered n = u*4+g
__device__ float g_bias2e[G4];
__device__ __half g_whh1p[16 * WTILEH];
__device__ __half g_wih2p[16 * WTILEH];
__device__ __half g_whh2p[16 * WTILEH];
__device__ __half g_wih1p[3 * WTILEH];
__device__ __half g_xp[NT * XSTEPH];

// ---------------- PTX helpers ----------------
__device__ __forceinline__ uint32_t smem_u32(const void* p) {
    uint32_t a;
    asm("{ .reg .u64 t; cvta.to.shared.u64 t, %1; cvt.u32.u64 %0, t; }" : "=r"(a) : "l"(p));
    return a;
}
__device__ __forceinline__ void cpbulk(uint32_t dst, const void* src, uint32_t bytes, uint32_t mbar) {
    asm volatile("cp.async.bulk.shared::cta.global.mbarrier::complete_tx::bytes [%0], [%1], %2, [%3];"
                 :: "r"(dst), "l"(src), "r"(bytes), "r"(mbar) : "memory");
}
#define MBAR_INIT(a, cnt) asm volatile("mbarrier.init.shared.b64 [%0], %1;" :: "r"(a), "r"(cnt) : "memory")
#define MBAR_EXPECT_TX(a, bytes) \
    asm volatile("mbarrier.arrive.expect_tx.shared.b64 _, [%0], %1;" :: "r"(a), "r"((uint32_t)(bytes)) : "memory")
#define MBAR_ARRIVE(a) \
    asm volatile("mbarrier.arrive.shared.b64 _, [%0];" :: "r"(a) : "memory")
#define MBAR_WAIT(a, par) do {                                                   \
    uint32_t _d = 0;                                                             \
    while (!_d) {                                                                \
        asm volatile("{ .reg .pred p; mbarrier.try_wait.parity.shared.b64 p, [%1], %2; selp.b32 %0,1,0,p; }" \
            : "=r"(_d) : "r"(a), "r"((uint32_t)(par)) : "memory");               \
    }                                                                            \
} while (0)

__device__ __forceinline__ void ldsm4(uint32_t* r, uint32_t addr) {
    asm volatile("ldmatrix.sync.aligned.m8n8.x4.shared.b16 {%0,%1,%2,%3}, [%4];"
                 : "=r"(r[0]), "=r"(r[1]), "=r"(r[2]), "=r"(r[3]) : "r"(addr));
}
__device__ __forceinline__ void mma16816(float* d, const uint32_t* a, const uint32_t* b) {
    asm volatile(
        "mma.sync.aligned.m16n8k16.row.col.f32.f16.f16.f32 "
        "{%0,%1,%2,%3}, {%4,%5,%6,%7}, {%8,%9}, {%0,%1,%2,%3};"
        : "+f"(d[0]), "+f"(d[1]), "+f"(d[2]), "+f"(d[3])
        : "r"(a[0]), "r"(a[1]), "r"(a[2]), "r"(a[3]), "r"(b[0]), "r"(b[1]));
}

__device__ __forceinline__ float sigf(float x) { return 1.0f / (1.0f + __expf(-x)); }
__device__ __forceinline__ float tanh_f(float x) { return 2.0f / (1.0f + __expf(-2.0f * x)) - 1.0f; }

// swizzled half-index within a tile block row: row r, half-col kl (0..63)
__device__ __forceinline__ int swh(int r, int kl) {
    return ((kl * 2) ^ ((r & 7) << 4)) >> 1;
}

// ---------------- single merged prep kernel ----------------
__device__ __forceinline__ void conv_w_packed(const float* W, __half* out, int K, int KP, int idx) {
    if (idx >= G4 * KP) return;
    int n = idx / KP, k = idx % KP;
    int g = n & 3, u = n >> 2;
    float v = (k < K) ? W[(size_t)(g * HD + u) * K + k] : 0.0f;
    int tile = k >> 6, kl = k & 63;
    out[(size_t)tile * WTILEH + (size_t)n * 64 + swh(n, kl)] = __float2half(v);
}

__global__ void prep_all(const float* __restrict__ x,
                         const float* __restrict__ h1, const float* __restrict__ c1,
                         const float* __restrict__ h2, const float* __restrict__ c2,
                         const float* __restrict__ bih1, const float* __restrict__ bhh1,
                         const float* __restrict__ bih2, const float* __restrict__ bhh2,
                         const float* __restrict__ Wih1, const float* __restrict__ Whh1,
                         const float* __restrict__ Wih2, const float* __restrict__ Whh2) {
    int idx = blockIdx.x * blockDim.x + threadIdx.x;
    int task = blockIdx.y;
    if (task == 0) {
        if (idx < NB * HD) {
            int m = idx / HD, u = idx % HD;
            int tile = u >> 6, kl = u & 63;
            size_t base = (size_t)tile * ATILEH + (size_t)m * 64 + swh(m, kl);
            g_h1e[0][base] = __float2half(h1[idx]);
            g_h2e[0][base] = __float2half(h2[idx]);
            g_c1[idx] = c1[idx];
            g_c2[idx] = c2[idx];
        }
        if (idx < G4) {
            int g = idx & 3, u = idx >> 2;
            int r = g * HD + u;
            g_bias1e[idx] = bih1[r] + bhh1[r];
            g_bias2e[idx] = bih2[r] + bhh2[r];
        }
    } else if (task == 1) {
        conv_w_packed(Whh1, g_whh1p, HD, HD, idx);
    } else if (task == 2) {
        conv_w_packed(Wih2, g_wih2p, HD, HD, idx);
    } else if (task == 3) {
        conv_w_packed(Whh2, g_whh2p, HD, HD, idx);
    } else if (task == 4) {
        conv_w_packed(Wih1, g_wih1p, IN, INP, idx);
    } else {
        if (idx >= NT * NB * INP) return;
        int k = idx % INP;
        int r = idx / INP;
        int b = r % NB, t = r / NB;
        float v = (k < IN) ? x[((size_t)b * NT + t) * IN + k] : 0.0f;
        int tile = k >> 6, kl = k & 63;
        g_xp[(size_t)t * XSTEPH + (size_t)tile * ATILEH + (size_t)b * 64 + swh(b, kl)] = __float2half(v);
    }
}

// ---------------- combined LSTM step kernel ----------------
// tl = 0..NT.  blockIdx.z==1: role1 (phase1 at t=tl-1)  [skip tl==0]
//              blockIdx.z==0: role0 (phase0 at t=tl)    [skip tl==NT]
// grid = (64 n-tiles, 1, 2 roles) = 128 CTAs, 1/SM. block = 512 (16 warps, 16m x 32n).
// Producer/consumer mbarrier pipeline (no __syncthreads in mainloop).
// Single fp16 activations: one mma pass per k-tile (4 mma / kk).
__global__ void __launch_bounds__(512)
lstm_step_combined(int tl) {
    const int role = blockIdx.z;
    if (role == 0 && tl == NT) return;
    if (role == 1 && tl == 0) return;
    const int t = (role == 0) ? tl : (tl - 1);
    const int cur = t & 1;
    const int n0 = blockIdx.x * 64;

    extern __shared__ __align__(16) char raw[];
    const uint32_t SB = (smem_u32(raw) + 1023u) & ~1023u;
    char* base = raw + (SB - smem_u32(raw));
    float* Gs    = (float*)base;                       // aliases stages (after loop)
    float* biasS = (float*)(base + SMEM_BODY + 128);   // after mbarriers
    const uint32_t MBF = SB + SMEM_BODY;               // 4 full barriers
    const uint32_t MBE = MBF + 32;                     // 4 empty barriers

    const int tid  = threadIdx.x;
    const int wid  = tid >> 5;
    const int lane = tid & 31;

    const __half *Ap0, *Ap1, *Bp0, *Bp1;
    const float* biasE;
    float* cst;
    __half* houtP;
    int T1;
    if (role == 0) {
        Ap0 = g_h1e[cur];      Bp0 = g_whh1p;
        Ap1 = g_xp + (size_t)t * XSTEPH;  Bp1 = g_wih1p;
        T1 = 3;
        biasE = g_bias1e; cst = g_c1; houtP = g_h1e[cur ^ 1];
    } else {
        Ap0 = g_h1e[cur ^ 1];  Bp0 = g_wih2p;
        Ap1 = g_h2e[cur];      Bp1 = g_whh2p;
        T1 = 16;
        biasE = g_bias2e; cst = g_c2; houtP = g_h2e[cur ^ 1];
    }
    const int T0 = 16;
    const int TT = T0 + T1;          // 32 or 19

    if (tid == 0) {
#pragma unroll
        for (int s = 0; s < NST; s++) {
            MBAR_INIT(MBF + 8 * s, 1);
            MBAR_INIT(MBE + 8 * s, 16);
        }
    }
    __syncthreads();

    auto issue = [&](int c) {
        const int s = c & (NST - 1);
        const __half *sa, *sb;
        if (c < T0) { sa = Ap0 + (size_t)c * ATILEH;        sb = Bp0 + ((size_t)c * 4096 + n0) * 64; }
        else        { sa = Ap1 + (size_t)(c - T0) * ATILEH; sb = Bp1 + ((size_t)(c - T0) * 4096 + n0) * 64; }
        const uint32_t mb = MBF + 8u * s;
        MBAR_EXPECT_TX(mb, ATB + BTB);
        cpbulk(SB + s * STB, sa, ATB, mb);
        cpbulk(SB + s * STB + ATB, sb, BTB, mb);
    };
    if (tid == 0) { issue(0); issue(1); issue(2); }

    float biasR = (tid < 64) ? biasE[n0 + tid] : 0.0f;

    // ldmatrix lane maps (SW128 swizzle; rows are 128B)
    const int wr = wid >> 1;      // m sixteenth (0..7), rows wr*16..+15
    const int wc = wid & 1;       // n half
    const int grp = lane >> 3, lr = lane & 7;
    const uint32_t xm = (uint32_t)(lr << 4);
    const uint32_t arowH = (uint32_t)((wr * 16 + lr + (grp & 1) * 8) * 128);
    uint32_t brow[2];
#pragma unroll
    for (int nc = 0; nc < 2; nc++)
        brow[nc] = (uint32_t)((wc * 32 + nc * 16 + lr + (grp >> 1) * 8) * 128) + ATB;
    uint32_t acol[4], bcol[4];
#pragma unroll
    for (int kk = 0; kk < 4; kk++) {
        acol[kk] = (uint32_t)(((grp >> 1) * 16 + kk * 32)) ^ xm;
        bcol[kk] = (uint32_t)(((grp & 1) * 16 + kk * 32)) ^ xm;
    }

    float d[4][4];
#pragma unroll
    for (int nj = 0; nj < 4; nj++)
#pragma unroll
        for (int q = 0; q < 4; q++) d[nj][q] = 0.0f;

    for (int c = 0; c < TT; c++) {
        const int s = c & (NST - 1);

        // producer: refill stage (c+3)&3 once tile c-1 consumers drained it
        if (tid == 0 && c + 3 < TT) {
            if (c >= 1) {
                const int cn = c + 3;
                MBAR_WAIT(MBE + 8u * (cn & (NST - 1)), (uint32_t)(((cn >> 2) - 1) & 1));
            }
            issue(c + 3);
        }

        // consumer: wait for this tile's data
        MBAR_WAIT(MBF + 8u * s, (uint32_t)((c >> 2) & 1));

        const uint32_t sb = SB + s * STB;
#pragma unroll
        for (int kk = 0; kk < 4; kk++) {
            uint32_t ar[4], b0r[4], b1r[4];
            ldsm4(b0r, sb + brow[0] + bcol[kk]);
            ldsm4(b1r, sb + brow[1] + bcol[kk]);
            ldsm4(ar,  sb + arowH + acol[kk]);
            mma16816(d[0], ar, b0r + 0);
            mma16816(d[1], ar, b0r + 2);
            mma16816(d[2], ar, b1r + 0);
            mma16816(d[3], ar, b1r + 2);
        }
        if (lane == 0) MBAR_ARRIVE(MBE + 8u * s);   // this warp done with stage s
    }
    __syncthreads();   // re-converge warps; stage smem now reusable as Gs

    if (tid < 64) biasS[tid] = biasR;

    // acc -> Gs [n][m]
#pragma unroll
    for (int nj = 0; nj < 4; nj++) {
        int r0 = wr * 16 + (lane >> 2);
        int cb = wc * 32 + nj * 8 + (lane & 3) * 2;
        Gs[cb * GS_STRIDE + r0]           = d[nj][0];
        Gs[(cb + 1) * GS_STRIDE + r0]     = d[nj][1];
        Gs[cb * GS_STRIDE + r0 + 8]       = d[nj][2];
        Gs[(cb + 1) * GS_STRIDE + r0 + 8] = d[nj][3];
    }
    __syncthreads();

    // cell update: 128 m x 16 u = 2048 cells, 4 per thread; h written packed+swizzled
    const int ubase = n0 >> 2;
#pragma unroll
    for (int r = 0; r < 4; r++) {
        int idx = tid + r * 512;
        int ml = idx & 127;     // m
        int u  = idx >> 7;      // 0..15
        int nb = u * 4;
        float gi_ = Gs[(nb + 0) * GS_STRIDE + ml] + biasS[nb + 0];
        float gf_ = Gs[(nb + 1) * GS_STRIDE + ml] + biasS[nb + 1];
        float gg_ = Gs[(nb + 2) * GS_STRIDE + ml] + biasS[nb + 2];
        float go_ = Gs[(nb + 3) * GS_STRIDE + ml] + biasS[nb + 3];
        int ug = ubase + u;
        int off = ml * HD + ug;
        float cv = cst[off];
        float cn = sigf(gf_) * cv + sigf(gi_) * tanh_f(gg_);
        cst[off] = cn;
        float h = sigf(go_) * tanh_f(cn);
        int tile = ug >> 6, kl = ug & 63;
        houtP[(size_t)tile * ATILEH + (size_t)ml * 64 + swh(ml, kl)] = __float2half(h);
    }
}

// ---------------- final FC: out = h2 @ Wfc^T + bfc ----------------
__global__ void fc_kernel(const float* __restrict__ Wfc, const float* __restrict__ bfc,
                          float* __restrict__ out) {
    int b = blockIdx.x;
    int c = blockIdx.y;
    int lane = threadIdx.x;
    // last phase1 (t=NT-1, odd) wrote g_h2e[0]
    const __half* he = g_h2e[0];
    const float* w = Wfc + (size_t)c * HD;
    float s = 0.0f;
    for (int k = lane; k < HD; k += 32) {
        int tile = k >> 6, kl = k & 63;
        float h = __half2float(he[(size_t)tile * ATILEH + (size_t)b * 64 + swh(b, kl)]);
        s += h * w[k];
    }
#pragma unroll
    for (int o = 16; o > 0; o >>= 1) s += __shfl_xor_sync(0xFFFFFFFFu, s, o);
    if (lane == 0) out[b * NC + c] = s + bfc[c];
}

// ---------------- launch ----------------
extern "C" void kernel_launch(void* const* d_in, const int* in_sizes, int n_in,
                              void* d_out, int out_size) {
    (void)in_sizes; (void)n_in; (void)out_size;
    const float* x    = (const float*)d_in[0];
    const float* h1   = (const float*)d_in[1];
    const float* c1   = (const float*)d_in[2];
    const float* h2   = (const float*)d_in[3];
    const float* c2   = (const float*)d_in[4];
    const float* Wih1 = (const float*)d_in[5];
    const float* Whh1 = (const float*)d_in[6];
    const float* bih1 = (const float*)d_in[7];
    const float* bhh1 = (const float*)d_in[8];
    const float* Wih2 = (const float*)d_in[9];
    const float* Whh2 = (const float*)d_in[10];
    const float* bih2 = (const float*)d_in[11];
    const float* bhh2 = (const float*)d_in[12];
    const float* Wfc  = (const float*)d_in[13];
    const float* bfc  = (const float*)d_in[14];
    float* out = (float*)d_out;

    static int smem_set = 0;
    if (!smem_set) {
        cudaFuncSetAttribute(lstm_step_combined, cudaFuncAttributeMaxDynamicSharedMemorySize, SMEM_DYN);
        smem_set = 1;
    }

    // one-time prep (single launch)
    {
        dim3 pgrid((NT * NB * INP + 255) / 256, 6);
        prep_all<<<pgrid, 256>>>(x, h1, c1, h2, c2, bih1, bhh1, bih2, bhh2,
                                 Wih1, Whh1, Wih2, Whh2);
    }

    // recurrence: one combined launch per step boundary
    dim3 grid(G4 / 64, 1, 2);   // 128 CTAs
    for (int tl = 0; tl <= NT; tl++) {
        lstm_step_combined<<<grid, 512, SMEM_DYN>>>(tl);
    }

    fc_kernel<<<dim3(NB, NC), 32>>>(Wfc, bfc, out);
}